// round 4
// baseline (speedup 1.0000x reference)
#include <cuda_runtime.h>
#include <cstdint>

#define DD 1024
#define HH 4096
#define EE 8
#define TT 4096
#define BM 128
#define BNC 128
#define BK 32
#define NS 3
#define RP 9216

// ---------------- scratch (device globals; no allocation) ----------------
__device__ float g_H[(size_t)RP * HH];      // gelu output, rna-rounded + k-permuted
__device__ float g_Y[(size_t)RP * DD];      // expert outputs (plain layout)
__device__ float g_Xc[(size_t)TT * DD];     // x, rna-rounded + k-permuted
__device__ float g_W1c[(size_t)EE * HH * DD];
__device__ float g_W2c[(size_t)EE * DD * HH];
__device__ float g_topw[TT * 2];
__device__ int   g_topi[TT * 2];
__device__ int   g_rows[TT * 2];
__device__ int   g_perm[RP];
__device__ int   g_cnt[EE];
__device__ int   g_poff[EE + 1];
__device__ int   g_cur[EE];

// ---------------- helpers ----------------
__device__ __forceinline__ uint32_t smem_u32(const void* p) {
    uint32_t a;
    asm("{ .reg .u64 t; cvta.to.shared.u64 t, %1; cvt.u32.u64 %0, t; }" : "=r"(a) : "l"(p));
    return a;
}
__device__ __forceinline__ float to_tf32(float x) {
    uint32_t r;
    asm("cvt.rna.tf32.f32 %0, %1;" : "=r"(r) : "f"(x));
    return __uint_as_float(r);
}
__device__ __forceinline__ void mma_tf32(float* d,
                                         float a0, float a1, float a2, float a3,
                                         float b0, float b1) {
    asm volatile("mma.sync.aligned.m16n8k8.row.col.f32.tf32.tf32.f32 "
                 "{%0,%1,%2,%3}, {%4,%5,%6,%7}, {%8,%9}, {%0,%1,%2,%3};"
                 : "+f"(d[0]), "+f"(d[1]), "+f"(d[2]), "+f"(d[3])
                 : "r"(__float_as_uint(a0)), "r"(__float_as_uint(a1)),
                   "r"(__float_as_uint(a2)), "r"(__float_as_uint(a3)),
                   "r"(__float_as_uint(b0)), "r"(__float_as_uint(b1)));
}
__device__ __forceinline__ float gelu_exact(float v) {
    return 0.5f * v * (1.0f + erff(v * 0.70710678118654752440f));
}
__device__ __forceinline__ void cp16(uint32_t dst, const void* src) {
    asm volatile("cp.async.cg.shared.global [%0], [%1], 16;" :: "r"(dst), "l"(src) : "memory");
}
#define CP_COMMIT() asm volatile("cp.async.commit_group;" ::: "memory")
#define CP_WAIT1()  asm volatile("cp.async.wait_group 1;" ::: "memory")
// chunk swizzle: conflict-free for both LDGSTS writes and frag reads
__device__ __forceinline__ uint32_t fsw(uint32_t g) { return ((g & 1u) << 2) | (g >> 1); }

// ---------------- small kernels ----------------
__global__ void init_kernel() {
    if (threadIdx.x < EE) g_cnt[threadIdx.x] = 0;
}

// transpose-permute + rna round for BOTH weight tensors in one grid:
// per 16-float group, out[j] = rna(in[(j%4)*4+j/4])
__global__ void convert_permute2(const float* __restrict__ s1, float* __restrict__ d1,
                                 const float* __restrict__ s2, float* __restrict__ d2,
                                 int ngroups_each) {
    int gidx = blockIdx.x * blockDim.x + threadIdx.x;
    const float* src;
    float* dst;
    int gg;
    if (gidx < ngroups_each)      { src = s1; dst = d1; gg = gidx; }
    else if (gidx < 2 * ngroups_each) { src = s2; dst = d2; gg = gidx - ngroups_each; }
    else return;
    const float4* s = (const float4*)(src + (size_t)gg * 16);
    float4 i0 = s[0], i1 = s[1], i2 = s[2], i3 = s[3];
    float4* d = (float4*)(dst + (size_t)gg * 16);
    d[0] = make_float4(to_tf32(i0.x), to_tf32(i1.x), to_tf32(i2.x), to_tf32(i3.x));
    d[1] = make_float4(to_tf32(i0.y), to_tf32(i1.y), to_tf32(i2.y), to_tf32(i3.y));
    d[2] = make_float4(to_tf32(i0.z), to_tf32(i1.z), to_tf32(i2.z), to_tf32(i3.z));
    d[3] = make_float4(to_tf32(i0.w), to_tf32(i1.w), to_tf32(i2.w), to_tf32(i3.w));
}

// one warp per token: logits -> softmax -> top2 -> counts; also emits g_Xc
__global__ void router_kernel(const float* __restrict__ x,
                              const float* __restrict__ Wr,
                              const float* __restrict__ br) {
    __shared__ float sWr[EE * DD];
    int tid = threadIdx.x;
    for (int i = tid; i < EE * DD / 4; i += blockDim.x)
        ((float4*)sWr)[i] = ((const float4*)Wr)[i];
    __syncthreads();

    int warp = (blockIdx.x * blockDim.x + tid) >> 5;
    int lane = tid & 31;
    const float4* xv = (const float4*)(x + (size_t)warp * DD);

    float acc[EE];
#pragma unroll
    for (int e = 0; e < EE; e++) acc[e] = 0.f;
#pragma unroll
    for (int i = 0; i < DD / 128; i++) {
        float4 xs = xv[lane + i * 32];
#pragma unroll
        for (int e = 0; e < EE; e++) {
            float4 w = ((const float4*)(sWr + e * DD))[lane + i * 32];
            acc[e] += xs.x * w.x + xs.y * w.y + xs.z * w.z + xs.w * w.w;
        }
    }
#pragma unroll
    for (int r = 0; r < 2; r++) {
        int grp = lane + r * 32;
        const float4* s = xv + grp * 4;
        float4 i0 = s[0], i1 = s[1], i2 = s[2], i3 = s[3];
        float4* d = (float4*)(g_Xc + (size_t)warp * DD + grp * 16);
        d[0] = make_float4(to_tf32(i0.x), to_tf32(i1.x), to_tf32(i2.x), to_tf32(i3.x));
        d[1] = make_float4(to_tf32(i0.y), to_tf32(i1.y), to_tf32(i2.y), to_tf32(i3.y));
        d[2] = make_float4(to_tf32(i0.z), to_tf32(i1.z), to_tf32(i2.z), to_tf32(i3.z));
        d[3] = make_float4(to_tf32(i0.w), to_tf32(i1.w), to_tf32(i2.w), to_tf32(i3.w));
    }
#pragma unroll
    for (int e = 0; e < EE; e++)
#pragma unroll
        for (int off = 16; off > 0; off >>= 1)
            acc[e] += __shfl_xor_sync(0xffffffffu, acc[e], off);

    if (lane == 0) {
        float lg[EE];
        float m = -1e30f;
#pragma unroll
        for (int e = 0; e < EE; e++) { lg[e] = acc[e] + br[e]; m = fmaxf(m, lg[e]); }
        float s = 0.f;
#pragma unroll
        for (int e = 0; e < EE; e++) { lg[e] = expf(lg[e] - m); s += lg[e]; }
        float inv = 1.f / s;
        int i0 = 0; float v0 = lg[0];
#pragma unroll
        for (int e = 1; e < EE; e++) if (lg[e] > v0) { v0 = lg[e]; i0 = e; }
        int i1 = -1; float v1 = -1.f;
#pragma unroll
        for (int e = 0; e < EE; e++) if (e != i0 && lg[e] > v1) { v1 = lg[e]; i1 = e; }
        g_topi[2 * warp]     = i0;
        g_topi[2 * warp + 1] = i1;
        g_topw[2 * warp]     = v0 * inv;
        g_topw[2 * warp + 1] = v1 * inv;
        atomicAdd(&g_cnt[i0], 1);
        atomicAdd(&g_cnt[i1], 1);
    }
}

__global__ void offsets_kernel() {
    if (threadIdx.x == 0) {
        int off = 0;
        for (int e = 0; e < EE; e++) {
            g_poff[e] = off;
            g_cur[e]  = off;
            off += ((g_cnt[e] + BM - 1) / BM) * BM;
        }
        g_poff[EE] = off;
    }
}

__global__ void scatter_kernel() {
    int idx = blockIdx.x * blockDim.x + threadIdx.x;
    if (idx >= 2 * TT) return;
    int e = g_topi[idx];
    int pos = atomicAdd(&g_cur[e], 1);
    g_rows[idx] = pos;
    g_perm[pos] = idx >> 1;
}

// ---------------- cp.async tf32 grouped GEMM (2 CTAs/SM) ----------------
#define A_ST (BM * BK * 4)      // 16 KB
#define B_ST (BNC * BK * 4)     // 16 KB
#define STG_B (A_ST + B_ST)     // 32 KB
#define GEMM_SMEM (NS * STG_B)  // 96 KB -> 2 CTAs per SM

template <bool PHASE1>
__global__ __launch_bounds__(128, 2)
void gemm_tf32(const float* __restrict__ Bw, const float* __restrict__ bias) {
    constexpr int N = PHASE1 ? HH : DD;
    constexpr int K = PHASE1 ? DD : HH;
    constexpr int NC = K / BK;

    const int m0 = blockIdx.y * BM;
    const int n0 = blockIdx.x * BNC;
    if (m0 >= g_poff[EE]) return;
    int e = 0;
#pragma unroll
    for (int i = 0; i < EE; i++) if (m0 >= g_poff[i + 1]) e = i + 1;

    extern __shared__ char smem[];
    const uint32_t smem_base = smem_u32(smem);
    const int tid  = threadIdx.x;
    const int warp = tid >> 5, lane = tid & 31;
    const int g = lane >> 2, t = lane & 3;
    const int wr = warp >> 1, wc = warp & 1;       // 2x2 warps, 64x64 each

    // ---- copy assignments: thread tid owns A row tid (8 chunks) + B row tid (8 chunks)
    const float* Abase = PHASE1 ? g_Xc : g_H;
    size_t arIdx = PHASE1 ? (size_t)g_perm[m0 + tid] : (size_t)(m0 + tid);
    const char* aSrc = (const char*)(Abase + arIdx * (size_t)K);
    const char* bSrc = (const char*)(Bw + ((size_t)e * N + n0 + tid) * (size_t)K);
    const uint32_t rowsw = fsw((uint32_t)(tid & 7));
    const uint32_t aBase = (uint32_t)tid * (BK * 4);
    const uint32_t bBase = A_ST + (uint32_t)tid * (BK * 4);

    // ---- fragment read offsets ----
    const uint32_t fg = fsw((uint32_t)g);
    const uint32_t ck0 = ((uint32_t)t ^ fg) << 4;
    const uint32_t ck1 = ((uint32_t)(t + 4) ^ fg) << 4;

    float acc[4][8][4];
#pragma unroll
    for (int i = 0; i < 4; i++)
#pragma unroll
        for (int j = 0; j < 8; j++)
#pragma unroll
            for (int r = 0; r < 4; r++) acc[i][j][r] = 0.f;

    auto issue = [&](int c) {
        uint32_t sb = smem_base + (c % NS) * STG_B;
        const char* as = aSrc + c * (BK * 4);
        const char* bs = bSrc + c * (BK * 4);
#pragma unroll
        for (int i = 0; i < 8; i++) cp16(sb + aBase + (((uint32_t)i ^ rowsw) << 4), as + i * 16);
#pragma unroll
        for (int i = 0; i < 8; i++) cp16(sb + bBase + (((uint32_t)i ^ rowsw) << 4), bs + i * 16);
    };

    issue(0); CP_COMMIT();
    issue(1); CP_COMMIT();

    for (int c = 0; c < NC; ++c) {
        CP_WAIT1();
        __syncthreads();
        if (c + 2 < NC) issue(c + 2);
        CP_COMMIT();

        const char* stg = smem + (c % NS) * STG_B;
#pragma unroll
        for (int kg = 0; kg < 2; kg++) {
            const uint32_t ck = kg ? ck1 : ck0;
            float4 al[4], ah[4];
#pragma unroll
            for (int mt = 0; mt < 4; mt++) {
                uint32_t ar = (uint32_t)(wr * 64 + mt * 16 + g) * (BK * 4);
                al[mt] = *(const float4*)(stg + ar + ck);
                ah[mt] = *(const float4*)(stg + ar + 8 * (BK * 4) + ck);
            }
#pragma unroll
            for (int h = 0; h < 2; h++) {
                float4 bf[4];
#pragma unroll
                for (int q = 0; q < 4; q++) {
                    uint32_t br_ = A_ST + (uint32_t)(wc * 64 + (h * 4 + q) * 8 + g) * (BK * 4);
                    bf[q] = *(const float4*)(stg + br_ + ck);
                }
#pragma unroll
                for (int mt = 0; mt < 4; mt++)
#pragma unroll
                    for (int q = 0; q < 4; q++) {
                        mma_tf32(acc[mt][h * 4 + q],
                                 al[mt].x, ah[mt].x, al[mt].y, ah[mt].y, bf[q].x, bf[q].y);
                        mma_tf32(acc[mt][h * 4 + q],
                                 al[mt].z, ah[mt].z, al[mt].w, ah[mt].w, bf[q].z, bf[q].w);
                    }
            }
        }
    }

    // ---- epilogue ----
    const float* biasp = bias + (size_t)e * N;
    if (PHASE1) {
#pragma unroll
        for (int mt = 0; mt < 4; mt++) {
            int r0 = m0 + wr * 64 + mt * 16 + g;
#pragma unroll
            for (int nt = 0; nt < 8; nt++) {
                int nb = n0 + wc * 64 + nt * 8 + 2 * t;
#pragma unroll
                for (int j = 0; j < 4; j++) {
                    int n = nb + (j & 1);
                    int row = (j < 2) ? r0 : r0 + 8;
                    float v = acc[mt][nt][j] + biasp[n];
                    v = to_tf32(gelu_exact(v));
                    int m16 = n & 15;
                    int p = (n & ~15) | (((m16 & 3) << 2) | (m16 >> 2));
                    g_H[(size_t)row * HH + p] = v;
                }
            }
        }
    } else {
#pragma unroll
        for (int mt = 0; mt < 4; mt++) {
            int r0 = m0 + wr * 64 + mt * 16 + g;
#pragma unroll
            for (int nt = 0; nt < 8; nt++) {
                int nb = n0 + wc * 64 + nt * 8 + 2 * t;
                float b0v = biasp[nb], b1v = biasp[nb + 1];
                *(float2*)&g_Y[(size_t)r0 * DD + nb] =
                    make_float2(acc[mt][nt][0] + b0v, acc[mt][nt][1] + b1v);
                *(float2*)&g_Y[(size_t)(r0 + 8) * DD + nb] =
                    make_float2(acc[mt][nt][2] + b0v, acc[mt][nt][3] + b1v);
            }
        }
    }
}

__global__ void combine_kernel(float* __restrict__ out) {
    int tk = blockIdx.x;
    int d4 = threadIdx.x;
    int r0 = g_rows[2 * tk], r1 = g_rows[2 * tk + 1];
    float w0 = g_topw[2 * tk], w1 = g_topw[2 * tk + 1];
    float4 y0 = *(const float4*)&g_Y[(size_t)r0 * DD + d4 * 4];
    float4 y1 = *(const float4*)&g_Y[(size_t)r1 * DD + d4 * 4];
    float4 o;
    o.x = w0 * y0.x + w1 * y1.x;
    o.y = w0 * y0.y + w1 * y1.y;
    o.z = w0 * y0.z + w1 * y1.z;
    o.w = w0 * y0.w + w1 * y1.w;
    ((float4*)out)[(size_t)tk * (DD / 4) + d4] = o;
}

// ---------------- launch ----------------
extern "C" void kernel_launch(void* const* d_in, const int* in_sizes, int n_in,
                              void* d_out, int out_size) {
    const float* x  = (const float*)d_in[0];
    const float* Wr = (const float*)d_in[1];
    const float* br = (const float*)d_in[2];
    const float* W1 = (const float*)d_in[3];
    const float* b1 = (const float*)d_in[4];
    const float* W2 = (const float*)d_in[5];
    const float* b2 = (const float*)d_in[6];
    float* out = (float*)d_out;
    (void)in_sizes; (void)n_in; (void)out_size;

    static int init_attr = 0;
    if (!init_attr) {
        cudaFuncSetAttribute(gemm_tf32<true>,  cudaFuncAttributeMaxDynamicSharedMemorySize, GEMM_SMEM);
        cudaFuncSetAttribute(gemm_tf32<false>, cudaFuncAttributeMaxDynamicSharedMemorySize, GEMM_SMEM);
        init_attr = 1;
    }

    float* w1c; cudaGetSymbolAddress((void**)&w1c, g_W1c);
    float* w2c; cudaGetSymbolAddress((void**)&w2c, g_W2c);

    const int wgroups = EE * HH * DD / 16;   // 2,097,152 per tensor
    init_kernel<<<1, 32>>>();
    convert_permute2<<<(2 * wgroups + 255) / 256, 256>>>(W1, w1c, W2, w2c, wgroups);
    router_kernel<<<TT / 8, 256>>>(x, Wr, br);
    offsets_kernel<<<1, 1>>>();
    scatter_kernel<<<(2 * TT + 255) / 256, 256>>>();
    gemm_tf32<true ><<<dim3(HH / BNC, RP / BM), 128, GEMM_SMEM>>>(w1c, b1);
    gemm_tf32<false><<<dim3(DD / BNC, RP / BM), 128, GEMM_SMEM>>>(w2c, b2);
    combine_kernel<<<TT, 256>>>(out);
}

// round 5
// speedup vs baseline: 2.3963x; 2.3963x over previous
#include <cuda_runtime.h>
#include <cuda_fp16.h>
#include <cstdint>

#define DD 1024
#define HH 4096
#define EE 8
#define TT 4096
#define BM 128
#define BNC 256
#define BK 64            // fp16 elements per stage-chunk (128B rows)
#define NS 4
#define RP 9216

// ---------------- scratch (device globals; no allocation) ----------------
__device__ __half g_Hh[(size_t)RP * HH];    // gelu output, fp16
__device__ float  g_Y[(size_t)RP * DD];     // expert outputs fp32
__device__ __half g_Xh[(size_t)TT * DD];    // x in fp16
__device__ __half g_W1h[(size_t)EE * HH * DD];
__device__ __half g_W2h[(size_t)EE * DD * HH];
__device__ float g_topw[TT * 2];
__device__ int   g_topi[TT * 2];
__device__ int   g_rows[TT * 2];
__device__ int   g_perm[RP];
__device__ int   g_cnt[EE];
__device__ int   g_poff[EE + 1];
__device__ int   g_cur[EE];

// ---------------- helpers ----------------
__device__ __forceinline__ uint32_t smem_u32(const void* p) {
    uint32_t a;
    asm("{ .reg .u64 t; cvta.to.shared.u64 t, %1; cvt.u32.u64 %0, t; }" : "=r"(a) : "l"(p));
    return a;
}
__device__ __forceinline__ void ldsm4(uint32_t& r0, uint32_t& r1, uint32_t& r2, uint32_t& r3,
                                      uint32_t addr) {
    asm volatile("ldmatrix.sync.aligned.m8n8.x4.shared.b16 {%0,%1,%2,%3}, [%4];"
                 : "=r"(r0), "=r"(r1), "=r"(r2), "=r"(r3) : "r"(addr));
}
__device__ __forceinline__ void mma_f16(float* d, uint32_t a0, uint32_t a1, uint32_t a2,
                                        uint32_t a3, uint32_t b0, uint32_t b1) {
    asm volatile("mma.sync.aligned.m16n8k16.row.col.f32.f16.f16.f32 "
                 "{%0,%1,%2,%3}, {%4,%5,%6,%7}, {%8,%9}, {%0,%1,%2,%3};"
                 : "+f"(d[0]), "+f"(d[1]), "+f"(d[2]), "+f"(d[3])
                 : "r"(a0), "r"(a1), "r"(a2), "r"(a3), "r"(b0), "r"(b1));
}
__device__ __forceinline__ float gelu_exact(float v) {
    return 0.5f * v * (1.0f + erff(v * 0.70710678118654752440f));
}
__device__ __forceinline__ void cp16(uint32_t dst, const void* src) {
    asm volatile("cp.async.cg.shared.global [%0], [%1], 16;" :: "r"(dst), "l"(src) : "memory");
}
#define CP_COMMIT() asm volatile("cp.async.commit_group;" ::: "memory")
#define CP_WAIT2()  asm volatile("cp.async.wait_group 2;" ::: "memory")

// ---------------- small kernels ----------------
__global__ void init_kernel() {
    if (threadIdx.x < EE) g_cnt[threadIdx.x] = 0;
}

// fp32 -> fp16 for both weight tensors, 8 elems/thread
__global__ void convert_h2(const float* __restrict__ s1, __half* __restrict__ d1,
                           const float* __restrict__ s2, __half* __restrict__ d2,
                           int n8each) {
    int i = blockIdx.x * blockDim.x + threadIdx.x;
    const float* s; __half* d; int g;
    if (i < n8each)            { s = s1; d = d1; g = i; }
    else if (i < 2 * n8each)   { s = s2; d = d2; g = i - n8each; }
    else return;
    float4 f0 = ((const float4*)s)[2 * g], f1 = ((const float4*)s)[2 * g + 1];
    __half2 h0 = __floats2half2_rn(f0.x, f0.y), h1 = __floats2half2_rn(f0.z, f0.w);
    __half2 h2 = __floats2half2_rn(f1.x, f1.y), h3 = __floats2half2_rn(f1.z, f1.w);
    uint4 o;
    o.x = *(uint32_t*)&h0; o.y = *(uint32_t*)&h1;
    o.z = *(uint32_t*)&h2; o.w = *(uint32_t*)&h3;
    ((uint4*)d)[g] = o;
}

// one warp per token: logits -> softmax -> top2 -> counts; also emits g_Xh (fp16)
__global__ void router_kernel(const float* __restrict__ x,
                              const float* __restrict__ Wr,
                              const float* __restrict__ br) {
    __shared__ float sWr[EE * DD];
    int tid = threadIdx.x;
    for (int i = tid; i < EE * DD / 4; i += blockDim.x)
        ((float4*)sWr)[i] = ((const float4*)Wr)[i];
    __syncthreads();

    int warp = (blockIdx.x * blockDim.x + tid) >> 5;
    int lane = tid & 31;
    const float4* xv = (const float4*)(x + (size_t)warp * DD);

    float acc[EE];
#pragma unroll
    for (int e = 0; e < EE; e++) acc[e] = 0.f;
#pragma unroll
    for (int i = 0; i < DD / 128; i++) {
        float4 xs = xv[lane + i * 32];
#pragma unroll
        for (int e = 0; e < EE; e++) {
            float4 w = ((const float4*)(sWr + e * DD))[lane + i * 32];
            acc[e] += xs.x * w.x + xs.y * w.y + xs.z * w.z + xs.w * w.w;
        }
    }
    // emit fp16 x row: 128 groups of 8 floats, 4 per lane
#pragma unroll
    for (int r = 0; r < 4; r++) {
        int g = lane + r * 32;
        float4 f0 = xv[2 * g], f1 = xv[2 * g + 1];
        __half2 h0 = __floats2half2_rn(f0.x, f0.y), h1 = __floats2half2_rn(f0.z, f0.w);
        __half2 h2 = __floats2half2_rn(f1.x, f1.y), h3 = __floats2half2_rn(f1.z, f1.w);
        uint4 o;
        o.x = *(uint32_t*)&h0; o.y = *(uint32_t*)&h1;
        o.z = *(uint32_t*)&h2; o.w = *(uint32_t*)&h3;
        ((uint4*)(g_Xh + (size_t)warp * DD))[g] = o;
    }
#pragma unroll
    for (int e = 0; e < EE; e++)
#pragma unroll
        for (int off = 16; off > 0; off >>= 1)
            acc[e] += __shfl_xor_sync(0xffffffffu, acc[e], off);

    if (lane == 0) {
        float lg[EE];
        float m = -1e30f;
#pragma unroll
        for (int e = 0; e < EE; e++) { lg[e] = acc[e] + br[e]; m = fmaxf(m, lg[e]); }
        float s = 0.f;
#pragma unroll
        for (int e = 0; e < EE; e++) { lg[e] = expf(lg[e] - m); s += lg[e]; }
        float inv = 1.f / s;
        int i0 = 0; float v0 = lg[0];
#pragma unroll
        for (int e = 1; e < EE; e++) if (lg[e] > v0) { v0 = lg[e]; i0 = e; }
        int i1 = -1; float v1 = -1.f;
#pragma unroll
        for (int e = 0; e < EE; e++) if (e != i0 && lg[e] > v1) { v1 = lg[e]; i1 = e; }
        g_topi[2 * warp]     = i0;
        g_topi[2 * warp + 1] = i1;
        g_topw[2 * warp]     = v0 * inv;
        g_topw[2 * warp + 1] = v1 * inv;
        atomicAdd(&g_cnt[i0], 1);
        atomicAdd(&g_cnt[i1], 1);
    }
}

__global__ void offsets_kernel() {
    if (threadIdx.x == 0) {
        int off = 0;
        for (int e = 0; e < EE; e++) {
            g_poff[e] = off;
            g_cur[e]  = off;
            off += ((g_cnt[e] + BM - 1) / BM) * BM;
        }
        g_poff[EE] = off;
    }
}

__global__ void scatter_kernel() {
    int idx = blockIdx.x * blockDim.x + threadIdx.x;
    if (idx >= 2 * TT) return;
    int e = g_topi[idx];
    int pos = atomicAdd(&g_cur[e], 1);
    g_rows[idx] = pos;
    g_perm[pos] = idx >> 1;
}

// ---------------- fp16 cp.async + ldmatrix grouped GEMM ----------------
#define A_ST (BM * BK * 2)      // 16 KB
#define B_ST (BNC * BK * 2)     // 32 KB
#define STG_B (A_ST + B_ST)     // 48 KB
#define GEMM_SMEM (NS * STG_B)  // 192 KB

template <bool PHASE1>
__global__ __launch_bounds__(256, 1)
void gemm_f16(const __half* __restrict__ Bw, const float* __restrict__ bias) {
    constexpr int N = PHASE1 ? HH : DD;
    constexpr int K = PHASE1 ? DD : HH;
    constexpr int NC = K / BK;

    const int m0 = blockIdx.y * BM;
    const int n0 = blockIdx.x * BNC;
    if (m0 >= g_poff[EE]) return;
    int e = 0;
#pragma unroll
    for (int i = 0; i < EE; i++) if (m0 >= g_poff[i + 1]) e = i + 1;

    extern __shared__ char smem[];
    const uint32_t smem_base = smem_u32(smem);
    const int tid  = threadIdx.x;
    const int warp = tid >> 5, lane = tid & 31;
    const int g = lane >> 2, t = lane & 3;
    const int wr = warp >> 2, wc = warp & 3;       // 2x4 warps, 64x64 each

    // ---- cp.async assignments (rows are 128B = 8 chunks of 16B) ----
    // A: thread -> row tid>>1, chunks (tid&1)*4 + 0..3
    const int arow = tid >> 1, acb = (tid & 1) * 4;
    const __half* Abase = PHASE1 ? g_Xh : g_Hh;
    size_t arIdx = PHASE1 ? (size_t)g_perm[m0 + arow] : (size_t)(m0 + arow);
    const char* aSrc = (const char*)(Abase + arIdx * (size_t)K) + acb * 16;
    uint32_t aDst[4];
#pragma unroll
    for (int i = 0; i < 4; i++)
        aDst[i] = (uint32_t)arow * 128 + ((uint32_t)((acb + i) ^ (arow & 7)) << 4);
    // B: thread -> row tid, chunks 0..7
    const char* bSrc = (const char*)(Bw + ((size_t)e * N + n0 + tid) * (size_t)K);
    uint32_t bDst[8];
#pragma unroll
    for (int i = 0; i < 8; i++)
        bDst[i] = A_ST + (uint32_t)tid * 128 + ((uint32_t)(i ^ (tid & 7)) << 4);

    // ---- ldmatrix lane addressing ----
    const int hiA = lane >> 4;            // 0/1 -> k chunk half
    const int hiB = (lane >> 3) & 1;
    uint32_t aOff[4], aXor[4];
#pragma unroll
    for (int mt = 0; mt < 4; mt++) {
        int r = wr * 64 + mt * 16 + (lane & 15);
        aOff[mt] = (uint32_t)r * 128;
        aXor[mt] = (uint32_t)(r & 7);
    }
    uint32_t bOff[4], bXor[4];
#pragma unroll
    for (int p = 0; p < 4; p++) {
        int r = wc * 64 + p * 16 + (lane & 7) + ((lane >> 4) << 3);
        bOff[p] = A_ST + (uint32_t)r * 128;
        bXor[p] = (uint32_t)(r & 7);
    }

    float acc[4][8][4];
#pragma unroll
    for (int i = 0; i < 4; i++)
#pragma unroll
        for (int j = 0; j < 8; j++)
#pragma unroll
            for (int r = 0; r < 4; r++) acc[i][j][r] = 0.f;

    auto issue = [&](int c) {
        uint32_t sb = smem_base + (c & 3) * STG_B;
        const char* as = aSrc + c * 128;
        const char* bs = bSrc + c * 128;
#pragma unroll
        for (int i = 0; i < 4; i++) cp16(sb + aDst[i], as + i * 16);
#pragma unroll
        for (int i = 0; i < 8; i++) cp16(sb + bDst[i], bs + i * 16);
    };

    issue(0); CP_COMMIT();
    issue(1); CP_COMMIT();
    issue(2); CP_COMMIT();

    for (int c = 0; c < NC; ++c) {
        CP_WAIT2();
        __syncthreads();
        if (c + 3 < NC) issue(c + 3);
        CP_COMMIT();

        const uint32_t stg = smem_base + (c & 3) * STG_B;
#pragma unroll
        for (int ks = 0; ks < 4; ks++) {
            uint32_t a[4][4];
#pragma unroll
            for (int mt = 0; mt < 4; mt++) {
                uint32_t ad = stg + aOff[mt] + (((uint32_t)(2 * ks + hiA) ^ aXor[mt]) << 4);
                ldsm4(a[mt][0], a[mt][1], a[mt][2], a[mt][3], ad);
            }
            uint32_t b[8][2];
#pragma unroll
            for (int p = 0; p < 4; p++) {
                uint32_t bd = stg + bOff[p] + (((uint32_t)(2 * ks + hiB) ^ bXor[p]) << 4);
                ldsm4(b[2 * p][0], b[2 * p][1], b[2 * p + 1][0], b[2 * p + 1][1], bd);
            }
#pragma unroll
            for (int mt = 0; mt < 4; mt++)
#pragma unroll
                for (int nt = 0; nt < 8; nt++)
                    mma_f16(acc[mt][nt], a[mt][0], a[mt][1], a[mt][2], a[mt][3],
                            b[nt][0], b[nt][1]);
        }
    }

    // ---- epilogue ----
    const float* biasp = bias + (size_t)e * N;
    if (PHASE1) {
#pragma unroll
        for (int mt = 0; mt < 4; mt++) {
            int r0 = m0 + wr * 64 + mt * 16 + g;
#pragma unroll
            for (int nt = 0; nt < 8; nt++) {
                int nb = n0 + wc * 64 + nt * 8 + 2 * t;
                float b0v = biasp[nb], b1v = biasp[nb + 1];
                float v00 = gelu_exact(acc[mt][nt][0] + b0v);
                float v01 = gelu_exact(acc[mt][nt][1] + b1v);
                float v10 = gelu_exact(acc[mt][nt][2] + b0v);
                float v11 = gelu_exact(acc[mt][nt][3] + b1v);
                *(__half2*)&g_Hh[(size_t)r0 * HH + nb]       = __floats2half2_rn(v00, v01);
                *(__half2*)&g_Hh[(size_t)(r0 + 8) * HH + nb] = __floats2half2_rn(v10, v11);
            }
        }
    } else {
#pragma unroll
        for (int mt = 0; mt < 4; mt++) {
            int r0 = m0 + wr * 64 + mt * 16 + g;
#pragma unroll
            for (int nt = 0; nt < 8; nt++) {
                int nb = n0 + wc * 64 + nt * 8 + 2 * t;
                float b0v = biasp[nb], b1v = biasp[nb + 1];
                *(float2*)&g_Y[(size_t)r0 * DD + nb] =
                    make_float2(acc[mt][nt][0] + b0v, acc[mt][nt][1] + b1v);
                *(float2*)&g_Y[(size_t)(r0 + 8) * DD + nb] =
                    make_float2(acc[mt][nt][2] + b0v, acc[mt][nt][3] + b1v);
            }
        }
    }
}

__global__ void combine_kernel(float* __restrict__ out) {
    int tk = blockIdx.x;
    int d4 = threadIdx.x;
    int r0 = g_rows[2 * tk], r1 = g_rows[2 * tk + 1];
    float w0 = g_topw[2 * tk], w1 = g_topw[2 * tk + 1];
    float4 y0 = *(const float4*)&g_Y[(size_t)r0 * DD + d4 * 4];
    float4 y1 = *(const float4*)&g_Y[(size_t)r1 * DD + d4 * 4];
    float4 o;
    o.x = w0 * y0.x + w1 * y1.x;
    o.y = w0 * y0.y + w1 * y1.y;
    o.z = w0 * y0.z + w1 * y1.z;
    o.w = w0 * y0.w + w1 * y1.w;
    ((float4*)out)[(size_t)tk * (DD / 4) + d4] = o;
}

// ---------------- launch ----------------
extern "C" void kernel_launch(void* const* d_in, const int* in_sizes, int n_in,
                              void* d_out, int out_size) {
    const float* x  = (const float*)d_in[0];
    const float* Wr = (const float*)d_in[1];
    const float* br = (const float*)d_in[2];
    const float* W1 = (const float*)d_in[3];
    const float* b1 = (const float*)d_in[4];
    const float* W2 = (const float*)d_in[5];
    const float* b2 = (const float*)d_in[6];
    float* out = (float*)d_out;
    (void)in_sizes; (void)n_in; (void)out_size;

    static int init_attr = 0;
    if (!init_attr) {
        cudaFuncSetAttribute(gemm_f16<true>,  cudaFuncAttributeMaxDynamicSharedMemorySize, GEMM_SMEM);
        cudaFuncSetAttribute(gemm_f16<false>, cudaFuncAttributeMaxDynamicSharedMemorySize, GEMM_SMEM);
        init_attr = 1;
    }

    __half* w1h; cudaGetSymbolAddress((void**)&w1h, g_W1h);
    __half* w2h; cudaGetSymbolAddress((void**)&w2h, g_W2h);

    const int n8 = EE * HH * DD / 8;   // 4,194,304 per tensor
    init_kernel<<<1, 32>>>();
    convert_h2<<<(2 * n8 + 255) / 256, 256>>>(W1, w1h, W2, w2h, n8);
    router_kernel<<<TT / 8, 256>>>(x, Wr, br);
    offsets_kernel<<<1, 1>>>();
    scatter_kernel<<<(2 * TT + 255) / 256, 256>>>();
    gemm_f16<true ><<<dim3(HH / BNC, RP / BM), 256, GEMM_SMEM>>>(w1h, b1);
    gemm_f16<false><<<dim3(DD / BNC, RP / BM), 256, GEMM_SMEM>>>(w2h, b2);
    combine_kernel<<<TT, 256>>>(out);
}